// round 9
// baseline (speedup 1.0000x reference)
#include <cuda_runtime.h>
#include <cstdint>
#include <math.h>

#define NB  4
#define CIN 256
#define PL  128
#define HH  128
#define WW  128
#define HW  16384
#define KK  9
#define CK  1152   // PL*KK
#define LDP 136
#define LDK 36

// ---- scratch (device globals: allocation-free) ----
__device__ float g_out1_nchw[NB*PL*HW];
__device__ float g_out1_nhwc[NB*HW*PL];
__device__ float g_ident[NB*PL*HW];
__device__ float g_py[NB*KK*HW];
__device__ float g_px[NB*KK*HW];
__device__ float g_mk[NB*KK*HW];
__device__ float g_wOffP[CK*32];          // [tap*128+c][o<27 pad 32] (tf32 bits)
__device__ float g_wDcB[CK*PL];           // [K'=k*128+c][o]          (tf32 bits)
__device__ float g_w3T[PL*PL];            // [c][o]                   (tf32 bits)
__device__ float g_w1T[CIN*PL];           // [c][o]                   (tf32 bits)
__device__ float g_wdsT[CIN*PL];          // [c][o]                   (tf32 bits)

// ---- tf32 mma helpers ----
__device__ __forceinline__ uint32_t f2tf(float x) {
    uint32_t r; asm("cvt.rna.tf32.f32 %0, %1;" : "=r"(r) : "f"(x)); return r;
}
__device__ __forceinline__ void mma_tf32(float d[4], const uint32_t a[4], const uint32_t b[2]) {
    asm volatile("mma.sync.aligned.m16n8k8.row.col.f32.tf32.tf32.f32 "
        "{%0,%1,%2,%3}, {%4,%5,%6,%7}, {%8,%9}, {%0,%1,%2,%3};"
        : "+f"(d[0]), "+f"(d[1]), "+f"(d[2]), "+f"(d[3])
        : "r"(a[0]), "r"(a[1]), "r"(a[2]), "r"(a[3]), "r"(b[0]), "r"(b[1]));
}

// ---------------- K0: weight transposes + tf32 conversion ----------------
__global__ void k_prep(const float* __restrict__ w_off,
                       const float* __restrict__ w_dc,
                       const float* __restrict__ w3,
                       const float* __restrict__ w1,
                       const float* __restrict__ wds) {
    int i = blockIdx.x * blockDim.x + threadIdx.x;
    if (i < CK*32) {
        int row = i >> 5, o = i & 31;
        int tap = row >> 7, c = row & 127;
        g_wOffP[i] = (o < 27) ? __uint_as_float(f2tf(w_off[o*CK + c*KK + tap])) : 0.f;
    }
    if (i < CK*PL) {
        int o = i & 127, t = i >> 7;
        int c = t & 127, k = t >> 7;
        g_wDcB[i] = __uint_as_float(f2tf(w_dc[(o*PL + c)*KK + k]));
    }
    if (i < CIN*PL) {
        int c = i >> 7, o = i & 127;
        g_w1T[i]  = __uint_as_float(f2tf(w1[o*CIN + c]));
        g_wdsT[i] = __uint_as_float(f2tf(wds[o*CIN + c]));
    }
    if (i < PL*PL) {
        int c = i >> 7, o = i & 127;
        g_w3T[i] = __uint_as_float(f2tf(w3[o*PL + c]));
    }
}

// ---------------- K1: conv1 / downsample via tf32 mma (pipelined) ----------------
#define SMEM_TOT_C (17408 * 4)
__global__ __launch_bounds__(256, 2) void k_cgemm(
    const float* __restrict__ x,
    const float* __restrict__ s1a, const float* __restrict__ t1a,
    const float* __restrict__ s1b, const float* __restrict__ t1b,
    const float* __restrict__ bds, const float* __restrict__ sd, const float* __restrict__ td)
{
    extern __shared__ __align__(16) float smf[];

    const int tid  = threadIdx.x;
    const int wrp  = tid >> 5;
    const int t3   = tid & 3;
    const int g    = (tid & 31) >> 2;
    const int m0   = (wrp & 3) * 32;
    const int n0   = (wrp >> 2) * 64;
    const int pos0 = blockIdx.x * 128;
    const int job  = blockIdx.y;
    const int b    = blockIdx.z;
    const float* wT = job ? g_wdsT : g_w1T;
    const float* xb = x + (size_t)b * CIN * HW + pos0;

    float acc[2][8][4];
#pragma unroll
    for (int mt = 0; mt < 2; mt++)
#pragma unroll
        for (int nt = 0; nt < 8; nt++)
#pragma unroll
            for (int i = 0; i < 4; i++) acc[mt][nt][i] = 0.f;

    float4 sa[2], sb[2];
    const int lrow = tid >> 5;
    const int lc4a = (tid & 31) * 4;
    auto ld = [&](int kc) {
#pragma unroll
        for (int u = 0; u < 2; u++) {
            int row = lrow + u*8;
            sa[u] = *(const float4*)&xb[(size_t)(kc*16 + row) * HW + lc4a];
            sb[u] = *(const float4*)&wT[(kc*16 + row)*PL + lc4a];
        }
    };
    auto sts = [&](int bf) {
        float* Ab = smf + bf * 2176;
        float* Bb = smf + 4352 + bf * 2176;
#pragma unroll
        for (int u = 0; u < 2; u++) {
            int row = lrow + u*8;
            uint4 tv = make_uint4(f2tf(sa[u].x), f2tf(sa[u].y), f2tf(sa[u].z), f2tf(sa[u].w));
            *(uint4*)&Ab[row*LDP + lc4a] = tv;
            *(float4*)&Bb[row*LDP + lc4a] = sb[u];
        }
    };

    ld(0); sts(0);
    __syncthreads();

    for (int kc = 0; kc < 16; kc++) {
        if (kc < 15) ld(kc + 1);
        const uint32_t* As = (const uint32_t*)(smf + (kc & 1) * 2176);
        const uint32_t* Bs = (const uint32_t*)(smf + 4352 + (kc & 1) * 2176);
#pragma unroll
        for (int ks = 0; ks < 16; ks += 8) {
            uint32_t a[2][4];
#pragma unroll
            for (int mt = 0; mt < 2; mt++) {
                int rb = m0 + mt*16 + g;
                a[mt][0] = As[(ks + t3)*LDP + rb];
                a[mt][1] = As[(ks + t3)*LDP + rb + 8];
                a[mt][2] = As[(ks + t3 + 4)*LDP + rb];
                a[mt][3] = As[(ks + t3 + 4)*LDP + rb + 8];
            }
#pragma unroll
            for (int nt = 0; nt < 8; nt++) {
                uint32_t bb[2];
                bb[0] = Bs[(ks + t3)*LDP + n0 + nt*8 + g];
                bb[1] = Bs[(ks + t3 + 4)*LDP + n0 + nt*8 + g];
                mma_tf32(acc[0][nt], a[0], bb);
                mma_tf32(acc[1][nt], a[1], bb);
            }
        }
        if (kc < 15) sts((kc + 1) & 1);
        __syncthreads();
    }

    float* Fs = smf;
#pragma unroll
    for (int nt = 0; nt < 8; nt++) {
        int c0 = n0 + nt*8 + 2*t3;
        float p0a, p0b, p0c, p0d, p1a, p1b, p1c, p1d;
        if (job == 0) {
            p0a = __ldg(s1a + c0);     p0b = __ldg(t1a + c0);
            p0c = __ldg(s1b + c0);     p0d = __ldg(t1b + c0);
            p1a = __ldg(s1a + c0 + 1); p1b = __ldg(t1a + c0 + 1);
            p1c = __ldg(s1b + c0 + 1); p1d = __ldg(t1b + c0 + 1);
        } else {
            p0a = __ldg(bds + c0);     p0b = __ldg(sd + c0);     p0c = __ldg(td + c0);
            p1a = __ldg(bds + c0 + 1); p1b = __ldg(sd + c0 + 1); p1c = __ldg(td + c0 + 1);
            p0d = p1d = 0.f;
        }
#pragma unroll
        for (int mt = 0; mt < 2; mt++) {
            int plo = m0 + mt*16 + g;
            float v0 = acc[mt][nt][0], v1 = acc[mt][nt][1];
            float v2 = acc[mt][nt][2], v3 = acc[mt][nt][3];
            if (job == 0) {
                v0 = fmaxf(fmaxf(v0 * p0a + p0b, 0.f) * p0c + p0d, 0.f);
                v2 = fmaxf(fmaxf(v2 * p0a + p0b, 0.f) * p0c + p0d, 0.f);
                v1 = fmaxf(fmaxf(v1 * p1a + p1b, 0.f) * p1c + p1d, 0.f);
                v3 = fmaxf(fmaxf(v3 * p1a + p1b, 0.f) * p1c + p1d, 0.f);
            } else {
                v0 = (v0 + p0a) * p0b + p0c;  v2 = (v2 + p0a) * p0b + p0c;
                v1 = (v1 + p1a) * p1b + p1c;  v3 = (v3 + p1a) * p1b + p1c;
            }
            Fs[c0*LDP + plo]           = v0;
            Fs[(c0 + 1)*LDP + plo]     = v1;
            Fs[c0*LDP + plo + 8]       = v2;
            Fs[(c0 + 1)*LDP + plo + 8] = v3;
        }
    }
    __syncthreads();

    const int o2 = tid & 127;
    const int ph = tid >> 7;
    float* dstN = (job == 0) ? g_out1_nchw : g_ident;
    {
        size_t base = ((size_t)(b*PL + o2))*HW + pos0 + ph*64;
        const float* frow = Fs + o2*LDP + ph*64;
#pragma unroll
        for (int i = 0; i < 16; i++)
            *(float4*)&dstN[base + i*4] = *(const float4*)&frow[i*4];
    }
    if (job == 0) {
        size_t base = ((size_t)(b*HW + pos0 + o2))*PL + ph*64;
#pragma unroll
        for (int i = 0; i < 16; i++) {
            int c = ph*64 + i*4;
            float4 v = make_float4(Fs[c*LDP + o2], Fs[(c+1)*LDP + o2],
                                   Fs[(c+2)*LDP + o2], Fs[(c+3)*LDP + o2]);
            *(float4*)&g_out1_nhwc[base + i*4] = v;
        }
    }
}

// ---------------- K2: offset/mask 3x3 conv via tf32 mma (pipelined) ----------------
#define OLDB 40
__global__ __launch_bounds__(256) void k_offset(const float* __restrict__ b_off) {
    __shared__ __align__(16) float Ao[2][16*LDP];
    __shared__ __align__(16) float Bo[2][16*OLDB];
    __shared__ __align__(16) float So[32*LDP];

    const int tid = threadIdx.x;
    const int wrp = tid >> 5;
    const int t3  = tid & 3;
    const int g   = (tid & 31) >> 2;
    const int m0  = wrp * 16;
    const int h   = blockIdx.x;
    const int b   = blockIdx.y;
    const float* inb = g_out1_nchw + (size_t)b * PL * HW;

    float acc[4][4];
#pragma unroll
    for (int nt = 0; nt < 4; nt++)
#pragma unroll
        for (int i = 0; i < 4; i++) acc[nt][i] = 0.f;

    float s_a[8], s_b[2];
    auto ld = [&](int kc) {
        const int tap = (kc*16) >> 7;
        const int c0  = (kc*16) & 127;
        const int ky  = tap / 3;
        const int kx  = tap - 3*ky;
        const int yy  = h + ky - 1;
        const bool rv = ((unsigned)yy < HH);
#pragma unroll
        for (int u = 0; u < 8; u++) {
            int idx = u*256 + tid;
            int kr = idx >> 7, p = idx & 127;
            int xp = p + kx - 1;
            float v = 0.f;
            if (rv && (unsigned)xp < WW)
                v = inb[(size_t)(c0 + kr)*HW + yy*WW + xp];
            s_a[u] = v;
        }
#pragma unroll
        for (int u = 0; u < 2; u++) {
            int idx = u*256 + tid;
            int kr = idx >> 5, o = idx & 31;
            s_b[u] = g_wOffP[(size_t)(kc*16 + kr)*32 + o];
        }
    };
    auto sts = [&](int bf) {
#pragma unroll
        for (int u = 0; u < 8; u++) {
            int idx = u*256 + tid;
            int kr = idx >> 7, p = idx & 127;
            Ao[bf][kr*LDP + p] = __uint_as_float(f2tf(s_a[u]));
        }
#pragma unroll
        for (int u = 0; u < 2; u++) {
            int idx = u*256 + tid;
            int kr = idx >> 5, o = idx & 31;
            Bo[bf][kr*OLDB + o] = s_b[u];
        }
    };

    ld(0); sts(0);
    __syncthreads();

    for (int kc = 0; kc < 72; kc++) {
        if (kc < 71) ld(kc + 1);
        const uint32_t* As = (const uint32_t*)Ao[kc & 1];
        const uint32_t* Bs = (const uint32_t*)Bo[kc & 1];
#pragma unroll
        for (int ks = 0; ks < 16; ks += 8) {
            uint32_t a[4];
            a[0] = As[(ks + t3)*LDP + m0 + g];
            a[1] = As[(ks + t3)*LDP + m0 + g + 8];
            a[2] = As[(ks + t3 + 4)*LDP + m0 + g];
            a[3] = As[(ks + t3 + 4)*LDP + m0 + g + 8];
#pragma unroll
            for (int nt = 0; nt < 4; nt++) {
                uint32_t bb[2];
                bb[0] = Bs[(ks + t3)*OLDB + nt*8 + g];
                bb[1] = Bs[(ks + t3 + 4)*OLDB + nt*8 + g];
                mma_tf32(acc[nt], a, bb);
            }
        }
        if (kc < 71) sts((kc + 1) & 1);
        __syncthreads();
    }

#pragma unroll
    for (int nt = 0; nt < 4; nt++) {
        int c0 = nt*8 + 2*t3;
        int plo = m0 + g;
        So[c0*LDP + plo]           = acc[nt][0];
        So[(c0 + 1)*LDP + plo]     = acc[nt][1];
        So[c0*LDP + plo + 8]       = acc[nt][2];
        So[(c0 + 1)*LDP + plo + 8] = acc[nt][3];
    }
    __syncthreads();

    const int p = tid & 127;
    const int half = tid >> 7;
    for (int k = half; k < 9; k += 2) {
        float dy = So[k*LDP + p]        + __ldg(b_off + k);
        float dx = So[(9 + k)*LDP + p]  + __ldg(b_off + 9 + k);
        float z  = So[(18 + k)*LDP + p] + __ldg(b_off + 18 + k);
        float mk = 1.f / (1.f + expf(-z));
        int idx = (b*KK + k)*HW + h*WW + p;
        g_py[idx] = (float)(h - 1 + k/3) + dy;
        g_px[idx] = (float)(p - 1 + k%3) + dx;
        g_mk[idx] = mk;
    }
}

// ---------------- K3: deform GEMM, dense gather, double-buffered + interleaved ----------------
// SMEM floats: A[2][128*36] @0 (9216), B[2][32*136] @9216 (8704), cE @17920 (9216) -> 27136
//              Vs [128*136] @0 (17408) ; B2 [16*136] @17408 (2176)   (reuse after mainloop)
#define SMF_A   0
#define SMF_B   9216
#define SMF_CE  17920
#define SMF_V   0
#define SMF_B2  17408
#define SMEM_TOT (27136 * 4)

__global__ __launch_bounds__(256, 2) void k_dgemm(
    const float* __restrict__ b_dc, const float* __restrict__ s2, const float* __restrict__ t2,
    const float* __restrict__ s3a, const float* __restrict__ t3a,
    const float* __restrict__ s3b, const float* __restrict__ t3b,
    float* __restrict__ out)
{
    extern __shared__ __align__(16) float smf[];
    float* cE = smf + SMF_CE;

    const int tid  = threadIdx.x;
    const int wrp  = tid >> 5;
    const int lane = tid & 31;
    const int t3   = tid & 3;
    const int g    = (tid & 31) >> 2;
    const int m0   = (wrp & 3) * 32;
    const int n0   = (wrp >> 2) * 64;
    const int sp   = lane >> 3;      // subpos 0..3
    const int cq   = lane & 7;       // channel quad 0..7
    const int pos0 = blockIdx.x * 128;
    const int b    = pos0 >> 14;
    const int pim0 = pos0 & (HW - 1);

    // precompute bilinear constants: cE[ci*8] = {w00,w01,w10,w11, i00,i01,i10,i11}
    for (int idx = tid; idx < 1152; idx += 256) {
        int k = idx >> 7, p = idx & 127;
        int gidx = (b*KK + k)*HW + pim0 + p;
        float py = g_py[gidx], px = g_px[gidx], mk = g_mk[gidx];
        float fy = floorf(py), fx = floorf(px);
        float wy = py - fy, wx = px - fx;
        int y0 = (int)fy, x0 = (int)fx;
        bool y0k = ((unsigned)y0 < HH), y1k = ((unsigned)(y0+1) < HH);
        bool x0k = ((unsigned)x0 < WW), x1k = ((unsigned)(x0+1) < WW);
        float w00 = (y0k && x0k) ? (1.f-wy)*(1.f-wx)*mk : 0.f;
        float w01 = (y0k && x1k) ? (1.f-wy)*wx*mk       : 0.f;
        float w10 = (y1k && x0k) ? wy*(1.f-wx)*mk       : 0.f;
        float w11 = (y1k && x1k) ? wy*wx*mk             : 0.f;
        int iy0 = min(max(y0, 0), HH-1),     ix0 = min(max(x0, 0), WW-1);
        int iy1 = min(max(y0 + 1, 0), HH-1), ix1 = min(max(x0 + 1, 0), WW-1);
        float* e = cE + idx*8;
        e[0] = w00; e[1] = w01; e[2] = w10; e[3] = w11;
        ((int*)e)[4] = (iy0*WW + ix0)*PL;
        ((int*)e)[5] = (iy0*WW + ix1)*PL;
        ((int*)e)[6] = (iy1*WW + ix0)*PL;
        ((int*)e)[7] = (iy1*WW + ix1)*PL;
    }
    __syncthreads();

    const float* nhwc = g_out1_nhwc + (size_t)b * HW * PL;

    float acc[2][8][4];
#pragma unroll
    for (int mt = 0; mt < 2; mt++)
#pragma unroll
        for (int nt = 0; nt < 8; nt++)
#pragma unroll
            for (int i = 0; i < 4; i++) acc[mt][nt][i] = 0.f;

    // prologue: fill chunk 0 into buf 0
    {
#pragma unroll
        for (int it = 0; it < 4; it++) {
            int p  = wrp*16 + it*4 + sp;
            const float4 wv = *(const float4*)(cE + p*8);
            const int4  iv  = *(const int4*)(cE + p*8 + 4);
            const float* base = nhwc + cq*4;
            float4 q0 = *(const float4*)(base + iv.x);
            float4 q1 = *(const float4*)(base + iv.y);
            float4 q2 = *(const float4*)(base + iv.z);
            float4 q3 = *(const float4*)(base + iv.w);
            float ox = q0.x*wv.x + q1.x*wv.y + q2.x*wv.z + q3.x*wv.w;
            float oy = q0.y*wv.x + q1.y*wv.y + q2.y*wv.z + q3.y*wv.w;
            float oz = q0.z*wv.x + q1.z*wv.y + q2.z*wv.z + q3.z*wv.w;
            float ow = q0.w*wv.x + q1.w*wv.y + q2.w*wv.z + q3.w*wv.w;
            uint4 tv = make_uint4(f2tf(ox), f2tf(oy), f2tf(oz), f2tf(ow));
            *(uint4*)&smf[SMF_A + p*LDK + cq*4] = tv;
            int qd = it*256 + tid, rr = qd >> 5, col4 = (qd & 31) * 4;
            *(float4*)&smf[SMF_B + rr*LDP + col4] =
                *(const float4*)&g_wDcB[(size_t)rr*PL + col4];
        }
    }
    __syncthreads();

    for (int kc = 0; kc < 36; kc++) {
        const int cur = kc & 1;
        const int nxt = cur ^ 1;
        const int kn  = kc + 1;
        const bool more = (kn < 36);
        const uint32_t* As = (const uint32_t*)(smf + SMF_A + cur*4608);
        const uint32_t* Bs = (const uint32_t*)(smf + SMF_B + cur*4352);
        float* An = smf + SMF_A + nxt*4608;
        float* Bn = smf + SMF_B + nxt*4352;
#pragma unroll
        for (int it = 0; it < 4; it++) {
            // ---- issue next-chunk loads for subfill `it` ----
            float4 q0, q1, q2, q3, wv, bw;
            int pA = 0, pB = 0;
            if (more) {
                int p  = wrp*16 + it*4 + sp;
                int ci = (kn >> 2)*128 + p;
                wv = *(const float4*)(cE + ci*8);
                const int4 iv = *(const int4*)(cE + ci*8 + 4);
                const float* base = nhwc + ((kn & 3) << 5) + cq*4;
                q0 = *(const float4*)(base + iv.x);
                q1 = *(const float4*)(base + iv.y);
                q2 = *(const float4*)(base + iv.z);
                q3 = *(const float4*)(base + iv.w);
                pA = p*LDK + cq*4;
                int qd = it*256 + tid, rr = qd >> 5, col4 = (qd & 31) * 4;
                bw = *(const float4*)&g_wDcB[((size_t)kn*32 + rr)*PL + col4];
                pB = rr*LDP + col4;
            }
            // ---- mma ks-block `it` of current chunk (covers the LDG latency) ----
            const int ks = it*8;
            uint32_t a[2][4];
#pragma unroll
            for (int mt = 0; mt < 2; mt++) {
                int rb = m0 + mt*16 + g;
                a[mt][0] = As[rb*LDK + ks + t3];
                a[mt][1] = As[(rb + 8)*LDK + ks + t3];
                a[mt][2] = As[rb*LDK + ks + t3 + 4];
                a[mt][3] = As[(rb + 8)*LDK + ks + t3 + 4];
            }
#pragma unroll
            for (int nt = 0; nt < 8; nt++) {
                uint32_t bb[2];
                bb[0] = Bs[(ks + t3)*LDP + n0 + nt*8 + g];
                bb[1] = Bs[(ks + t3 + 4)*LDP + n0 + nt*8 + g];
                mma_tf32(acc[0][nt], a[0], bb);
                mma_tf32(acc[1][nt], a[1], bb);
            }
            // ---- blend + store next-chunk tiles ----
            if (more) {
                float ox = q0.x*wv.x + q1.x*wv.y + q2.x*wv.z + q3.x*wv.w;
                float oy = q0.y*wv.x + q1.y*wv.y + q2.y*wv.z + q3.y*wv.w;
                float oz = q0.z*wv.x + q1.z*wv.y + q2.z*wv.z + q3.z*wv.w;
                float ow = q0.w*wv.x + q1.w*wv.y + q2.w*wv.z + q3.w*wv.w;
                uint4 tv = make_uint4(f2tf(ox), f2tf(oy), f2tf(oz), f2tf(ow));
                *(uint4*)&An[pA] = tv;
                *(float4*)&Bn[pB] = bw;
            }
        }
        __syncthreads();
    }

    // epilogue 1: v = relu(bn2(acc + b_dc)) -> Vs[c][pos] (tf32 bits)
    float* Vs = smf + SMF_V;
#pragma unroll
    for (int nt = 0; nt < 8; nt++) {
        int c0 = n0 + nt*8 + 2*t3;
        float b0 = __ldg(b_dc + c0),     ss0 = __ldg(s2 + c0),     tt0 = __ldg(t2 + c0);
        float b1 = __ldg(b_dc + c0 + 1), ss1 = __ldg(s2 + c0 + 1), tt1 = __ldg(t2 + c0 + 1);
#pragma unroll
        for (int mt = 0; mt < 2; mt++) {
            int plo = m0 + mt*16 + g;
            float v0 = fmaxf((acc[mt][nt][0] + b0) * ss0 + tt0, 0.f);
            float v1 = fmaxf((acc[mt][nt][1] + b1) * ss1 + tt1, 0.f);
            float v2 = fmaxf((acc[mt][nt][2] + b0) * ss0 + tt0, 0.f);
            float v3 = fmaxf((acc[mt][nt][3] + b1) * ss1 + tt1, 0.f);
            Vs[c0*LDP + plo]           = __uint_as_float(f2tf(v0));
            Vs[(c0 + 1)*LDP + plo]     = __uint_as_float(f2tf(v1));
            Vs[c0*LDP + plo + 8]       = __uint_as_float(f2tf(v2));
            Vs[(c0 + 1)*LDP + plo + 8] = __uint_as_float(f2tf(v3));
        }
    }
    __syncthreads();

    // GEMM2: conv3, K=128 in 8 chunks of 16
    float acc3[2][8][4];
#pragma unroll
    for (int mt = 0; mt < 2; mt++)
#pragma unroll
        for (int nt = 0; nt < 8; nt++)
#pragma unroll
            for (int i = 0; i < 4; i++) acc3[mt][nt][i] = 0.f;

    float* B2 = smf + SMF_B2;
    for (int cb = 0; cb < 8; cb++) {
        float4 r[2];
#pragma unroll
        for (int u = 0; u < 2; u++) {
            int qd = u*256 + tid, rr = qd >> 5, col4 = (qd & 31) * 4;
            r[u] = *(const float4*)&g_w3T[((size_t)cb*16 + rr)*PL + col4];
        }
        __syncthreads();
#pragma unroll
        for (int u = 0; u < 2; u++) {
            int qd = u*256 + tid, rr = qd >> 5, col4 = (qd & 31) * 4;
            *(float4*)&B2[rr*LDP + col4] = r[u];
        }
        __syncthreads();
        const uint32_t* As = (const uint32_t*)Vs;
        const uint32_t* Bs = (const uint32_t*)B2;
#pragma unroll
        for (int ks = 0; ks < 16; ks += 8) {
            uint32_t a[2][4];
#pragma unroll
            for (int mt = 0; mt < 2; mt++) {
                int rb = m0 + mt*16 + g;
                a[mt][0] = As[(cb*16 + ks + t3)*LDP + rb];
                a[mt][1] = As[(cb*16 + ks + t3)*LDP + rb + 8];
                a[mt][2] = As[(cb*16 + ks + t3 + 4)*LDP + rb];
                a[mt][3] = As[(cb*16 + ks + t3 + 4)*LDP + rb + 8];
            }
#pragma unroll
            for (int nt = 0; nt < 8; nt++) {
                uint32_t bb[2];
                bb[0] = Bs[(ks + t3)*LDP + n0 + nt*8 + g];
                bb[1] = Bs[(ks + t3 + 4)*LDP + n0 + nt*8 + g];
                mma_tf32(acc3[0][nt], a[0], bb);
                mma_tf32(acc3[1][nt], a[1], bb);
            }
        }
    }
    __syncthreads();

    // epilogue 2: bn3a/relu/bn3b -> Fs, then +identity coalesced store
    float* Fs = smf + SMF_V;
#pragma unroll
    for (int nt = 0; nt < 8; nt++) {
        int c0 = n0 + nt*8 + 2*t3;
        float sa0 = __ldg(s3a + c0),     ta0 = __ldg(t3a + c0);
        float sb0 = __ldg(s3b + c0),     tb0 = __ldg(t3b + c0);
        float sa1 = __ldg(s3a + c0 + 1), ta1 = __ldg(t3a + c0 + 1);
        float sb1 = __ldg(s3b + c0 + 1), tb1 = __ldg(t3b + c0 + 1);
#pragma unroll
        for (int mt = 0; mt < 2; mt++) {
            int plo = m0 + mt*16 + g;
            Fs[c0*LDP + plo]           = fmaxf(acc3[mt][nt][0] * sa0 + ta0, 0.f) * sb0 + tb0;
            Fs[(c0 + 1)*LDP + plo]     = fmaxf(acc3[mt][nt][1] * sa1 + ta1, 0.f) * sb1 + tb1;
            Fs[c0*LDP + plo + 8]       = fmaxf(acc3[mt][nt][2] * sa0 + ta0, 0.f) * sb0 + tb0;
            Fs[(c0 + 1)*LDP + plo + 8] = fmaxf(acc3[mt][nt][3] * sa1 + ta1, 0.f) * sb1 + tb1;
        }
    }
    __syncthreads();

    {
        const int o2 = tid & 127;
        const int ph = tid >> 7;
        size_t base = ((size_t)(b*PL + o2))*HW + pim0 + ph*64;
        const float* frow = Fs + o2*LDP + ph*64;
#pragma unroll
        for (int i = 0; i < 16; i++) {
            float4 f = *(const float4*)&frow[i*4];
            float4 id = *(const float4*)&g_ident[base + i*4];
            *(float4*)&out[base + i*4] = make_float4(
                fmaxf(f.x + id.x, 0.f), fmaxf(f.y + id.y, 0.f),
                fmaxf(f.z + id.z, 0.f), fmaxf(f.w + id.w, 0.f));
        }
    }
}

// ---------------- host ----------------
extern "C" void kernel_launch(void* const* d_in, const int* in_sizes, int n_in,
                              void* d_out, int out_size) {
    const float* x    = (const float*)d_in[0];
    const float* w1   = (const float*)d_in[1];
    const float* s1a  = (const float*)d_in[2];
    const float* t1a  = (const float*)d_in[3];
    const float* s1b  = (const float*)d_in[4];
    const float* t1b  = (const float*)d_in[5];
    const float* w_off= (const float*)d_in[6];
    const float* b_off= (const float*)d_in[7];
    const float* w_dc = (const float*)d_in[8];
    const float* b_dc = (const float*)d_in[9];
    const float* s2   = (const float*)d_in[10];
    const float* t2   = (const float*)d_in[11];
    const float* w3   = (const float*)d_in[12];
    const float* s3a  = (const float*)d_in[13];
    const float* t3a  = (const float*)d_in[14];
    const float* s3b  = (const float*)d_in[15];
    const float* t3b  = (const float*)d_in[16];
    const float* w_ds = (const float*)d_in[17];
    const float* b_ds = (const float*)d_in[18];
    const float* sd   = (const float*)d_in[19];
    const float* td   = (const float*)d_in[20];
    float* out = (float*)d_out;

    k_prep<<<(CK*PL + 255)/256, 256>>>(w_off, w_dc, w3, w1, w_ds);

    cudaFuncSetAttribute(k_cgemm, cudaFuncAttributeMaxDynamicSharedMemorySize, SMEM_TOT_C);
    dim3 g1(HW/128, 2, NB);
    k_cgemm<<<g1, 256, SMEM_TOT_C>>>(x, s1a, t1a, s1b, t1b, b_ds, sd, td);

    dim3 g2(HH, NB);
    k_offset<<<g2, 256>>>(b_off);

    cudaFuncSetAttribute(k_dgemm, cudaFuncAttributeMaxDynamicSharedMemorySize, SMEM_TOT);
    k_dgemm<<<NB*HW/128, 256, SMEM_TOT>>>(b_dc, s2, t2, s3a, t3a, s3b, t3b, out);
}